// round 5
// baseline (speedup 1.0000x reference)
#include <cuda_runtime.h>

#define NN   20000
#define FIN  128
#define HIDD 32
#define NH   8
#define HCC  256
#define EE   320000
#define ETOT (EE + NN)
#define NG   64
#define NCLS 10

// ---------------- device scratch (no allocations allowed) ----------------
__device__ float g_h[NN * HCC];        // features after GEMM (layer input to conv)
__device__ float g_out[NN * HCC];      // conv output
__device__ float g_al[NN * NH];        // per-node att_l projection
__device__ float g_ar[NN * NH];        // per-node att_r projection
__device__ int   g_deg[NN];
__device__ int   g_cur[NN];
__device__ int   g_rowptr[NN + 1];
__device__ int   g_col[ETOT];          // src indices, CSR by dst
__device__ float g_pooled[NG * HCC];
__device__ float g_cnt[NG];

// ---------------- helpers ----------------
__device__ __forceinline__ float warp_sum(float v) {
#pragma unroll
    for (int o = 16; o; o >>= 1) v += __shfl_xor_sync(0xffffffffu, v, o);
    return v;
}

// ---------------- zero scratch that must be zero each replay ----------------
__global__ void zero_prep_kernel() {
    int i = blockIdx.x * blockDim.x + threadIdx.x;
    if (i < NN) { g_deg[i] = 0; g_cur[i] = 0; }
    if (i < NG * HCC) g_pooled[i] = 0.f;
    if (i < NG) g_cnt[i] = 0.f;
}

// ---------------- CSR build (edge_index is int32: src[0..E), dst[E..2E)) ----
__global__ void deg_kernel(const int* __restrict__ edge) {
    int e = blockIdx.x * blockDim.x + threadIdx.x;
    if (e >= ETOT) return;
    int dst = (e < EE) ? edge[EE + e] : (e - EE);
    atomicAdd(&g_deg[dst], 1);
}

__global__ void scan_kernel() {
    __shared__ int sh[1024];
    const int CH = (NN + 1023) / 1024;  // 20
    int t = threadIdx.x;
    int base = t * CH;
    int sum = 0;
    for (int j = 0; j < CH; j++) {
        int idx = base + j;
        if (idx < NN) sum += g_deg[idx];
    }
    sh[t] = sum;
    __syncthreads();
    for (int off = 1; off < 1024; off <<= 1) {
        int v = 0;
        if (t >= off) v = sh[t - off];
        __syncthreads();
        sh[t] += v;
        __syncthreads();
    }
    int excl = sh[t] - sum;
    int run = excl;
    for (int j = 0; j < CH; j++) {
        int idx = base + j;
        if (idx < NN) { g_rowptr[idx] = run; run += g_deg[idx]; }
    }
    if (t == 1023) g_rowptr[NN] = run;  // = ETOT
}

__global__ void scatter_kernel(const int* __restrict__ edge) {
    int e = blockIdx.x * blockDim.x + threadIdx.x;
    if (e >= ETOT) return;
    int src, dst;
    if (e < EE) { src = edge[e]; dst = edge[EE + e]; }
    else        { src = dst = e - EE; }
    int pos = atomicAdd(&g_cur[dst], 1);
    g_col[g_rowptr[dst] + pos] = src;
}

// ---------------- tiled fp32 GEMM: g_h[M,Nc] = A[M,K] @ B[K,Nc] ----------------
// a_from_gout=0: A = A_ext (external input x). a_from_gout=1: A = g_out.
__global__ void gemm_kernel(const float* __restrict__ A_ext, const float* __restrict__ B,
                            int a_from_gout, int M, int K, int Nc) {
    const float* A = a_from_gout ? (const float*)g_out : A_ext;
    float* C = g_h;
    __shared__ float As[16][65];
    __shared__ float Bs[16][64];
    int tid = threadIdx.x;
    int tx = tid & 15, ty = tid >> 4;
    int row0 = blockIdx.x * 64, col0 = blockIdx.y * 64;
    float acc[4][4];
#pragma unroll
    for (int i = 0; i < 4; i++)
#pragma unroll
        for (int j = 0; j < 4; j++) acc[i][j] = 0.f;

    for (int k0 = 0; k0 < K; k0 += 16) {
        for (int i = tid; i < 64 * 16; i += 256) {
            int kk = i & 15, r = i >> 4;
            int gr = row0 + r;
            As[kk][r] = (gr < M) ? A[(long)gr * K + k0 + kk] : 0.f;
        }
        for (int i = tid; i < 16 * 64; i += 256) {
            int c = i & 63, kk = i >> 6;
            Bs[kk][c] = B[(long)(k0 + kk) * Nc + col0 + c];
        }
        __syncthreads();
#pragma unroll
        for (int kk = 0; kk < 16; kk++) {
            float a[4], b[4];
#pragma unroll
            for (int i = 0; i < 4; i++) a[i] = As[kk][ty * 4 + i];
#pragma unroll
            for (int j = 0; j < 4; j++) b[j] = Bs[kk][tx * 4 + j];
#pragma unroll
            for (int i = 0; i < 4; i++)
#pragma unroll
                for (int j = 0; j < 4; j++) acc[i][j] += a[i] * b[j];
        }
        __syncthreads();
    }
#pragma unroll
    for (int i = 0; i < 4; i++) {
        int r = row0 + ty * 4 + i;
        if (r >= M) continue;
#pragma unroll
        for (int j = 0; j < 4; j++) C[(long)r * Nc + col0 + tx * 4 + j] = acc[i][j];
    }
}

// ---------------- per-node attention projections a_l, a_r ----------------
__global__ void attproj_kernel(const float* __restrict__ attl, const float* __restrict__ attr) {
    int i = blockIdx.x;
    int w = threadIdx.x >> 5, lane = threadIdx.x & 31;
    float v = g_h[i * HCC + w * HIDD + lane];
    float al = warp_sum(v * attl[w * HIDD + lane]);
    float ar = warp_sum(v * attr[w * HIDD + lane]);
    if (lane == 0) {
        g_al[i * NH + w] = al;
        g_ar[i * NH + w] = ar;
    }
}

// ---------------- conv: one warp per (dst node, head), online softmax ----------------
__global__ void conv_kernel(const float* __restrict__ bias, int elu) {
    int i = blockIdx.x;
    int w = threadIdx.x >> 5, lane = threadIdx.x & 31;
    int base = i * HCC + w * HIDD + lane;
    float xi = g_h[base];
    float ar = g_ar[i * NH + w];
    int s = g_rowptr[i], e = g_rowptr[i + 1];
    float m = -1e30f, d = 0.f, acc = 0.f;
    for (int idx = s; idx < e; ++idx) {
        int j = g_col[idx];
        float xj = g_h[j * HCC + w * HIDD + lane];
        float t = warp_sum(xi * xj);                 // logits (dot per head)
        float sig = 1.f / (1.f + __expf(-t));
        float a = (g_al[j * NH + w] + ar) * sig;
        a = a > 0.f ? a : 0.2f * a;                  // leaky relu 0.2
        // online softmax update (warp-uniform branch)
        if (a <= m) {
            float p = __expf(a - m);
            d += p; acc += p * xj;
        } else {
            float sc = __expf(m - a);
            d = d * sc + 1.f; acc = acc * sc + xj; m = a;
        }
    }
    float val = acc / (d + 1e-16f) + bias[w * HIDD + lane];
    if (elu) val = val > 0.f ? val : expm1f(val);
    g_out[base] = val;
}

// ---------------- global mean pool (batch is int32) ----------------
__global__ void pool_kernel(const int* __restrict__ batch) {
    int idx = blockIdx.x * blockDim.x + threadIdx.x;
    if (idx >= NN * HCC) return;
    int n = idx / HCC, c = idx % HCC;
    int b = batch[n];
    atomicAdd(&g_pooled[b * HCC + c], g_out[idx]);
    if (c == 0) atomicAdd(&g_cnt[b], 1.f);
}

// ---------------- final linear ----------------
__global__ void final_kernel(const float* __restrict__ linW, const float* __restrict__ linb,
                             float* __restrict__ out) {
    int t = threadIdx.x;
    if (t >= NG * NCLS) return;
    int g = t / NCLS, c = t % NCLS;
    float cnt = g_cnt[g];
    if (cnt < 1.f) cnt = 1.f;
    float inv = 1.f / cnt;
    float sum = linb[c];
    for (int k = 0; k < HCC; k++)
        sum += g_pooled[g * HCC + k] * inv * linW[k * NCLS + c];
    out[g * NCLS + c] = sum;
}

// ---------------- launch ----------------
extern "C" void kernel_launch(void* const* d_in, const int* in_sizes, int n_in,
                              void* d_out, int out_size) {
    const float* x     = (const float*)d_in[0];
    const int*   edge  = (const int*)d_in[1];    // int32 (JAX x64 disabled)
    const int*   batch = (const int*)d_in[2];    // int32
    const float* W1    = (const float*)d_in[3];
    const float* attl1 = (const float*)d_in[4];
    const float* attr1 = (const float*)d_in[5];
    const float* b1    = (const float*)d_in[6];
    const float* W2    = (const float*)d_in[7];
    const float* attl2 = (const float*)d_in[8];
    const float* attr2 = (const float*)d_in[9];
    const float* b2    = (const float*)d_in[10];
    const float* linW  = (const float*)d_in[11];
    const float* linb  = (const float*)d_in[12];
    float* out = (float*)d_out;

    zero_prep_kernel<<<(NN + 255) / 256, 256>>>();
    deg_kernel<<<(ETOT + 255) / 256, 256>>>(edge);
    scan_kernel<<<1, 1024>>>();
    scatter_kernel<<<(ETOT + 255) / 256, 256>>>(edge);

    // layer 1
    gemm_kernel<<<dim3((NN + 63) / 64, HCC / 64), 256>>>(x, W1, 0, NN, FIN, HCC);
    attproj_kernel<<<NN, 256>>>(attl1, attr1);
    conv_kernel<<<NN, 256>>>(b1, 1);

    // layer 2
    gemm_kernel<<<dim3((NN + 63) / 64, HCC / 64), 256>>>(nullptr, W2, 1, NN, HCC, HCC);
    attproj_kernel<<<NN, 256>>>(attl2, attr2);
    conv_kernel<<<NN, 256>>>(b2, 0);

    // pool + head
    pool_kernel<<<(NN * HCC + 255) / 256, 256>>>(batch);
    final_kernel<<<1, 640>>>(linW, linb, out);
}

// round 7
// speedup vs baseline: 2.0048x; 2.0048x over previous
#include <cuda_runtime.h>

#define NN   20000
#define FIN  128
#define HIDD 32
#define NH   8
#define HCC  256
#define EE   320000
#define ETOT (EE + NN)
#define NG   64
#define NCLS 10

// ---------------- device scratch ----------------
__device__ float g_h[NN * HCC];        // features after GEMM (conv input)
__device__ float g_out[NN * HCC];      // conv output
__device__ float g_al[NN * NH];
__device__ float g_ar[NN * NH];
__device__ int   g_deg[NN];
__device__ int   g_cur[NN];
__device__ int   g_rowptr[NN + 1];
__device__ int   g_col[ETOT];          // CSR by dst
__device__ float g_pooled[NG * HCC];
__device__ float g_cnt[NG];

__device__ __forceinline__ float warp_sum(float v) {
#pragma unroll
    for (int o = 16; o; o >>= 1) v += __shfl_xor_sync(0xffffffffu, v, o);
    return v;
}

// ---------------- zero scratch ----------------
__global__ void zero_prep_kernel() {
    int i = blockIdx.x * blockDim.x + threadIdx.x;
    if (i < NN) { g_deg[i] = 0; g_cur[i] = 0; }
    if (i < NG * HCC) g_pooled[i] = 0.f;
    if (i < NG) g_cnt[i] = 0.f;
}

// ---------------- CSR build (edge_index int32: src[0..E), dst[E..2E)) ------
__global__ void deg_kernel(const int* __restrict__ edge) {
    int e = blockIdx.x * blockDim.x + threadIdx.x;
    if (e >= ETOT) return;
    int dst = (e < EE) ? edge[EE + e] : (e - EE);
    atomicAdd(&g_deg[dst], 1);
}

__global__ void scan_kernel() {
    __shared__ int sh[1024];
    const int CH = (NN + 1023) / 1024;
    int t = threadIdx.x;
    int base = t * CH;
    int sum = 0;
    for (int j = 0; j < CH; j++) {
        int idx = base + j;
        if (idx < NN) sum += g_deg[idx];
    }
    sh[t] = sum;
    __syncthreads();
    for (int off = 1; off < 1024; off <<= 1) {
        int v = 0;
        if (t >= off) v = sh[t - off];
        __syncthreads();
        sh[t] += v;
        __syncthreads();
    }
    int run = sh[t] - sum;
    for (int j = 0; j < CH; j++) {
        int idx = base + j;
        if (idx < NN) { g_rowptr[idx] = run; run += g_deg[idx]; }
    }
    if (t == 1023) g_rowptr[NN] = run;
}

__global__ void scatter_kernel(const int* __restrict__ edge) {
    int e = blockIdx.x * blockDim.x + threadIdx.x;
    if (e >= ETOT) return;
    int src, dst;
    if (e < EE) { src = edge[e]; dst = edge[EE + e]; }
    else        { src = dst = e - EE; }
    int pos = atomicAdd(&g_cur[dst], 1);
    g_col[g_rowptr[dst] + pos] = src;
}

// ---------------- GEMM: g_h[M,Nc] = A[M,K] @ B[K,Nc], 128x64 tile ----------
#define BM 128
#define BN 64
#define BK 16
__global__ void gemm_kernel(const float* __restrict__ A_ext, const float* __restrict__ B,
                            int a_from_gout, int M, int K, int Nc) {
    const float* A = a_from_gout ? (const float*)g_out : A_ext;
    float* C = g_h;
    __shared__ float As[BK][BM + 4];
    __shared__ float Bs[BK][BN];
    int tid = threadIdx.x;                 // 256
    int tx = tid & 15;                     // col group 0..15
    int ty = tid >> 4;                     // row group 0..15
    int row0 = blockIdx.x * BM, col0 = blockIdx.y * BN;
    float acc[8][4];
#pragma unroll
    for (int i = 0; i < 8; i++)
#pragma unroll
        for (int j = 0; j < 4; j++) acc[i][j] = 0.f;

    for (int k0 = 0; k0 < K; k0 += BK) {
        // A tile: 128 rows x 16 k = 512 float4, 2 per thread (coalesced along K)
#pragma unroll
        for (int i = 0; i < 2; i++) {
            int v = tid * 2 + i;           // 0..511
            int r = v >> 2;                // 0..127
            int kk = (v & 3) * 4;
            int gr = row0 + r;
            float4 av = make_float4(0.f, 0.f, 0.f, 0.f);
            if (gr < M) av = *(const float4*)&A[(size_t)gr * K + k0 + kk];
            As[kk + 0][r] = av.x; As[kk + 1][r] = av.y;
            As[kk + 2][r] = av.z; As[kk + 3][r] = av.w;
        }
        // B tile: 16 x 64 = 256 float4, 1 per thread
        {
            int kk = tid >> 4;
            int c = (tid & 15) * 4;
            *(float4*)&Bs[kk][c] = *(const float4*)&B[(size_t)(k0 + kk) * Nc + col0 + c];
        }
        __syncthreads();
#pragma unroll
        for (int kk = 0; kk < BK; kk++) {
            float4 a0 = *(float4*)&As[kk][ty * 8];
            float4 a1 = *(float4*)&As[kk][ty * 8 + 4];
            float4 b  = *(float4*)&Bs[kk][tx * 4];
            float ar_[8] = {a0.x, a0.y, a0.z, a0.w, a1.x, a1.y, a1.z, a1.w};
            float bc[4]  = {b.x, b.y, b.z, b.w};
#pragma unroll
            for (int i = 0; i < 8; i++)
#pragma unroll
                for (int j = 0; j < 4; j++) acc[i][j] += ar_[i] * bc[j];
        }
        __syncthreads();
    }
#pragma unroll
    for (int i = 0; i < 8; i++) {
        int r = row0 + ty * 8 + i;
        if (r >= M) continue;
        float4 v = make_float4(acc[i][0], acc[i][1], acc[i][2], acc[i][3]);
        *(float4*)&C[(size_t)r * Nc + col0 + tx * 4] = v;
    }
}

// ---------------- per-node attention projections ----------------
__global__ void attproj_kernel(const float* __restrict__ attl, const float* __restrict__ attr) {
    int i = blockIdx.x;
    int w = threadIdx.x >> 5, lane = threadIdx.x & 31;
    float v = g_h[i * HCC + w * HIDD + lane];
    float al = warp_sum(v * attl[w * HIDD + lane]);
    float ar = warp_sum(v * attr[w * HIDD + lane]);
    if (lane == 0) {
        g_al[i * NH + w] = al;
        g_ar[i * NH + w] = ar;
    }
}

// ---------------- conv: 1 warp = 4 heads of one dst node, branchless online softmax
// lane layout: group = lane>>3 (4 groups), sub = lane&7; group handles head base+group
// with channels head*32 + sub*4 .. +3 (float4 per lane).
__global__ void conv_kernel(const float* __restrict__ bias, int elu) {
    int warp = threadIdx.x >> 5;
    int lane = threadIdx.x & 31;
    int node = blockIdx.x * 4 + (warp >> 1);   // 8 warps -> 4 nodes
    int head = ((warp & 1) << 2) + (lane >> 3);
    int sub = lane & 7;
    int fofs = head * HIDD + sub * 4;
    int fbase = node * HCC + fofs;

    float4 xi = *(const float4*)&g_h[fbase];
    float ar = g_ar[node * NH + head];
    int s = g_rowptr[node], e = g_rowptr[node + 1];

    float m = -1e30f, d = 0.f;
    float4 acc = make_float4(0.f, 0.f, 0.f, 0.f);
    for (int idx = s; idx < e; ++idx) {
        int j = g_col[idx];
        float4 xj = *(const float4*)&g_h[j * HCC + fofs];
        float alj = g_al[j * NH + head];
        float t = xi.x * xj.x + xi.y * xj.y + xi.z * xj.z + xi.w * xj.w;
        t += __shfl_xor_sync(0xffffffffu, t, 4);
        t += __shfl_xor_sync(0xffffffffu, t, 2);
        t += __shfl_xor_sync(0xffffffffu, t, 1);
        float sig = 1.f / (1.f + __expf(-t));
        float a = (alj + ar) * sig;
        a = fmaxf(a, 0.2f * a);                 // leaky relu 0.2
        float mn = fmaxf(m, a);
        float so = __expf(m - mn);
        float p  = __expf(a - mn);
        d = d * so + p;
        m = mn;
        acc.x = acc.x * so + p * xj.x;
        acc.y = acc.y * so + p * xj.y;
        acc.z = acc.z * so + p * xj.z;
        acc.w = acc.w * so + p * xj.w;
    }
    float inv = 1.f / (d + 1e-16f);
    float4 bv = *(const float4*)&bias[fofs];
    float4 r;
    r.x = acc.x * inv + bv.x;
    r.y = acc.y * inv + bv.y;
    r.z = acc.z * inv + bv.z;
    r.w = acc.w * inv + bv.w;
    if (elu) {
        r.x = r.x > 0.f ? r.x : expm1f(r.x);
        r.y = r.y > 0.f ? r.y : expm1f(r.y);
        r.z = r.z > 0.f ? r.z : expm1f(r.z);
        r.w = r.w > 0.f ? r.w : expm1f(r.w);
    }
    *(float4*)&g_out[fbase] = r;
}

// ---------------- segmented mean pool (batch sorted) ----------------
__global__ void pool_kernel(const int* __restrict__ batch) {
    int c = threadIdx.x;                       // 256 channels
    int n0 = blockIdx.x * 128;
    int n1 = n0 + 128;
    if (n1 > NN) n1 = NN;
    float sum = 0.f;
    int cur = batch[n0];
    int cnt = 0;
    for (int n = n0; n < n1; n++) {
        int b = batch[n];
        if (b != cur) {
            atomicAdd(&g_pooled[cur * HCC + c], sum);
            if (c == 0) atomicAdd(&g_cnt[cur], (float)cnt);
            sum = 0.f; cnt = 0; cur = b;
        }
        sum += g_out[n * HCC + c];
        cnt++;
    }
    atomicAdd(&g_pooled[cur * HCC + c], sum);
    if (c == 0) atomicAdd(&g_cnt[cur], (float)cnt);
}

// ---------------- final linear ----------------
__global__ void final_kernel(const float* __restrict__ linW, const float* __restrict__ linb,
                             float* __restrict__ out) {
    int t = threadIdx.x;
    if (t >= NG * NCLS) return;
    int g = t / NCLS, c = t % NCLS;
    float cnt = g_cnt[g];
    if (cnt < 1.f) cnt = 1.f;
    float inv = 1.f / cnt;
    float sum = linb[c];
    for (int k = 0; k < HCC; k++)
        sum += g_pooled[g * HCC + k] * inv * linW[k * NCLS + c];
    out[g * NCLS + c] = sum;
}

// ---------------- launch ----------------
extern "C" void kernel_launch(void* const* d_in, const int* in_sizes, int n_in,
                              void* d_out, int out_size) {
    const float* x     = (const float*)d_in[0];
    const int*   edge  = (const int*)d_in[1];
    const int*   batch = (const int*)d_in[2];
    const float* W1    = (const float*)d_in[3];
    const float* attl1 = (const float*)d_in[4];
    const float* attr1 = (const float*)d_in[5];
    const float* b1    = (const float*)d_in[6];
    const float* W2    = (const float*)d_in[7];
    const float* attl2 = (const float*)d_in[8];
    const float* attr2 = (const float*)d_in[9];
    const float* b2    = (const float*)d_in[10];
    const float* linW  = (const float*)d_in[11];
    const float* linb  = (const float*)d_in[12];
    float* out = (float*)d_out;

    zero_prep_kernel<<<(NN + 255) / 256, 256>>>();
    deg_kernel<<<(ETOT + 255) / 256, 256>>>(edge);
    scan_kernel<<<1, 1024>>>();
    scatter_kernel<<<(ETOT + 255) / 256, 256>>>(edge);

    dim3 ggrid((NN + BM - 1) / BM, HCC / BN);

    // layer 1
    gemm_kernel<<<ggrid, 256>>>(x, W1, 0, NN, FIN, HCC);
    attproj_kernel<<<NN, 256>>>(attl1, attr1);
    conv_kernel<<<NN / 4, 256>>>(b1, 1);

    // layer 2
    gemm_kernel<<<ggrid, 256>>>(nullptr, W2, 1, NN, HCC, HCC);
    attproj_kernel<<<NN, 256>>>(attl2, attr2);
    conv_kernel<<<NN / 4, 256>>>(b2, 0);

    // pool + head
    pool_kernel<<<(NN + 127) / 128, 256>>>(batch);
    final_kernel<<<1, 640>>>(linW, linb, out);
}